// round 2
// baseline (speedup 1.0000x reference)
#include <cuda_runtime.h>

// Problem constants
#define BATCH    16
#define HW       (1024 * 1024)
#define HW4      (HW / 4)
#define GRIDX    74
#define NT       256
#define NQ       7            // focal, ce, p, p*t, t, bin, bin*t
#define SMOOTH   1e-6f
#define NBLOCKS  (GRIDX * BATCH)

// Per-block partials: [BATCH][GRIDX][8] (padded to 8 floats)
__device__ float        g_part[BATCH * GRIDX * 8];
__device__ unsigned int g_count;   // zero-initialized; self-resets each launch

struct Acc { float focal, ce, p, pt, t, bin, bint; };

__device__ __forceinline__ void accum(Acc& a, float x, float t) {
    // x ~ N(0,1): |x| <= ~6, so exp(-x) in [e^-6, e^6] — no overflow, no abs needed.
    float u   = __expf(-x);                  // EX2 (MUFU)
    float s   = 1.0f + u;
    float p   = __fdividef(1.0f, s);         // RCP (MUFU) : sigmoid(x)
    float lnS = __logf(s);                   // LG2 (MUFU) : log(1+exp(-x))
    // ce = softplus(x) - x*t = x + log(1+exp(-x)) - x*t = x*(1-t) + lnS
    float ce  = fmaf(x, 1.0f - t, lnS);
    // t in {0,1}: 1-p_t = t ? 1-p : p ; alpha_t = t ? 0.25 : 0.75
    float omp   = (t > 0.5f) ? (1.0f - p) : p;
    float alpha = 0.75f - 0.5f * t;
    a.focal = fmaf(alpha * ce, omp * omp, a.focal);
    a.ce   += ce;
    a.p    += p;
    a.pt    = fmaf(p, t, a.pt);
    a.t    += t;
    float b = (x > 0.0f) ? 1.0f : 0.0f;
    a.bin  += b;
    a.bint  = fmaf(b, t, a.bint);
}

__device__ __forceinline__ float warp_sum(float v) {
    #pragma unroll
    for (int off = 16; off > 0; off >>= 1)
        v += __shfl_xor_sync(0xFFFFFFFFu, v, off);
    return v;
}

__global__ __launch_bounds__(NT)
void loss_fused_kernel(const float4* __restrict__ pred,
                       const float4* __restrict__ gt,
                       const float*  __restrict__ pred_iou,
                       float*        __restrict__ out) {
    const int img = blockIdx.y;
    const float4* px = pred + (size_t)img * HW4;
    const float4* tx = gt   + (size_t)img * HW4;

    Acc a = {0.f, 0.f, 0.f, 0.f, 0.f, 0.f, 0.f};

    const int stride = GRIDX * NT;
    int i = blockIdx.x * NT + threadIdx.x;

    // unroll-2: batch 4x LDG.128 before compute (MLP_p1 = 4)
    for (; i + stride < HW4; i += 2 * stride) {
        float4 x0 = px[i];
        float4 t0 = tx[i];
        float4 x1 = px[i + stride];
        float4 t1 = tx[i + stride];
        accum(a, x0.x, t0.x); accum(a, x0.y, t0.y);
        accum(a, x0.z, t0.z); accum(a, x0.w, t0.w);
        accum(a, x1.x, t1.x); accum(a, x1.y, t1.y);
        accum(a, x1.z, t1.z); accum(a, x1.w, t1.w);
    }
    if (i < HW4) {
        float4 x0 = px[i];
        float4 t0 = tx[i];
        accum(a, x0.x, t0.x); accum(a, x0.y, t0.y);
        accum(a, x0.z, t0.z); accum(a, x0.w, t0.w);
    }

    // -------- block reduction --------
    float vals[NQ] = {a.focal, a.ce, a.p, a.pt, a.t, a.bin, a.bint};
    #pragma unroll
    for (int q = 0; q < NQ; q++) vals[q] = warp_sum(vals[q]);

    __shared__ float sm[NT / 32][NQ];
    const int lane = threadIdx.x & 31;
    const int warp = threadIdx.x >> 5;
    if (lane == 0) {
        #pragma unroll
        for (int q = 0; q < NQ; q++) sm[warp][q] = vals[q];
    }
    __syncthreads();

    if (warp == 0) {
        #pragma unroll
        for (int q = 0; q < NQ; q++) {
            float v = (lane < NT / 32) ? sm[lane][q] : 0.0f;
            v = warp_sum(v);
            if (lane == 0) vals[q] = v;
        }
        if (lane == 0) {
            float* dst = g_part + ((size_t)img * GRIDX + blockIdx.x) * 8;
            #pragma unroll
            for (int q = 0; q < NQ; q++) dst[q] = vals[q];
        }
    }

    // -------- last block performs the epilogue --------
    __shared__ bool is_last;
    __syncthreads();   // ensure g_part write issued (warp 0) before fence
    if (threadIdx.x == 0) {
        __threadfence();
        unsigned int v = atomicAdd(&g_count, 1u);
        is_last = (v == (unsigned int)(NBLOCKS - 1));
    }
    __syncthreads();
    if (!is_last) return;

    // 8 warps, 16 images: warp w handles images w and w+8
    __shared__ float agg[BATCH][4];
    for (int b = warp; b < BATCH; b += NT / 32) {
        float s[NQ] = {0.f, 0.f, 0.f, 0.f, 0.f, 0.f, 0.f};
        for (int j = lane; j < GRIDX; j += 32) {
            const float* q = g_part + ((size_t)b * GRIDX + j) * 8;
            #pragma unroll
            for (int k = 0; k < NQ; k++) s[k] += q[k];
        }
        #pragma unroll
        for (int k = 0; k < NQ; k++) s[k] = warp_sum(s[k]);
        if (lane == 0) {
            // s: 0=focal 1=ce 2=p 3=pt 4=t 5=bin 6=bint
            float dice_term = (2.0f * s[3] + SMOOTH) / (s[2] + s[4] + SMOOTH);
            float inter  = s[6];
            float uni    = s[5] + s[4] - s[6];
            float actual = (inter + SMOOTH) / (uni + SMOOTH);
            float d = pred_iou[b] - actual;
            agg[b][0] = s[0];
            agg[b][1] = s[1];
            agg[b][2] = dice_term;
            agg[b][3] = d * d;
        }
    }
    __syncthreads();

    if (threadIdx.x == 0) {
        float fsum = 0.f, csum = 0.f, dsum = 0.f, isum = 0.f;
        #pragma unroll
        for (int b = 0; b < BATCH; b++) {
            fsum += agg[b][0];
            csum += agg[b][1];
            dsum += agg[b][2];
            isum += agg[b][3];
        }
        const float invN = 1.0f / (float)((long long)BATCH * HW);
        float focal    = fsum * invN;
        float dice     = 1.0f - dsum / (float)BATCH;
        float boundary = csum * invN;           // focal + dice + 0.5*(2*mean(ce))
        float iou_loss = 0.1f * (isum / (float)BATCH);
        out[0] = focal + dice + boundary + iou_loss;
        g_count = 0;   // reset for next graph replay
    }
}

extern "C" void kernel_launch(void* const* d_in, const int* in_sizes, int n_in,
                              void* d_out, int out_size) {
    const float4* pred = (const float4*)d_in[0];
    const float4* gt   = (const float4*)d_in[1];
    const float*  piou = (const float*)d_in[2];
    float* out = (float*)d_out;

    dim3 grid(GRIDX, BATCH);
    loss_fused_kernel<<<grid, NT>>>(pred, gt, piou, out);
}

// round 3
// speedup vs baseline: 1.1945x; 1.1945x over previous
#include <cuda_runtime.h>

// Problem constants
#define BATCH    16
#define HW       (1024 * 1024)
#define HW4      (HW / 4)
#define GRIDX    74
#define NT       256
#define NQ       7            // focal, ce, p, p*t, t, bin, bin*t
#define SMOOTH   1e-6f
#define NBLOCKS  (GRIDX * BATCH)

// Per-block partials: [BATCH][GRIDX][8] (padded to 8 floats)
__device__ float        g_part[BATCH * GRIDX * 8];
__device__ unsigned int g_count;   // zero-initialized; self-resets each launch

struct Acc { float focal, ce, p, pt, t, bin, bint; };

__device__ __forceinline__ void accum(Acc& a, float x, float t) {
    // x ~ N(0,1): |x| small, exp(-x) never overflows in fp32 for |x| < 80.
    float u   = __expf(-x);                  // EX2 (MUFU)
    float s   = 1.0f + u;
    float p   = __fdividef(1.0f, s);         // RCP (MUFU) : sigmoid(x)
    float lnS = __logf(s);                   // LG2 (MUFU) : log(1+exp(-x))
    // ce = softplus(x) - x*t = x*(1-t) + log(1+exp(-x))
    float ce  = fmaf(x, 1.0f - t, lnS);
    // t in {0,1}: 1-p_t = t ? 1-p : p ; alpha_t = t ? 0.25 : 0.75
    float omp   = (t > 0.5f) ? (1.0f - p) : p;
    float alpha = 0.75f - 0.5f * t;
    a.focal = fmaf(alpha * ce, omp * omp, a.focal);
    a.ce   += ce;
    a.p    += p;
    a.pt    = fmaf(p, t, a.pt);
    a.t    += t;
    float b = (x > 0.0f) ? 1.0f : 0.0f;
    a.bin  += b;
    a.bint  = fmaf(b, t, a.bint);
}

__device__ __forceinline__ float warp_sum(float v) {
    #pragma unroll
    for (int off = 16; off > 0; off >>= 1)
        v += __shfl_xor_sync(0xFFFFFFFFu, v, off);
    return v;
}

__global__ __launch_bounds__(NT, 8)   // pin to 32 regs -> 8 CTAs/SM -> single wave
void loss_fused_kernel(const float4* __restrict__ pred,
                       const float4* __restrict__ gt,
                       const float*  __restrict__ pred_iou,
                       float*        __restrict__ out) {
    const int img = blockIdx.y;
    const float4* px = pred + (size_t)img * HW4;
    const float4* tx = gt   + (size_t)img * HW4;

    Acc a = {0.f, 0.f, 0.f, 0.f, 0.f, 0.f, 0.f};

    const int stride = GRIDX * NT;
    for (int i = blockIdx.x * NT + threadIdx.x; i < HW4; i += stride) {
        float4 xv = __ldg(px + i);
        float4 tv = __ldg(tx + i);
        accum(a, xv.x, tv.x);
        accum(a, xv.y, tv.y);
        accum(a, xv.z, tv.z);
        accum(a, xv.w, tv.w);
    }

    // -------- block reduction --------
    float vals[NQ] = {a.focal, a.ce, a.p, a.pt, a.t, a.bin, a.bint};
    #pragma unroll
    for (int q = 0; q < NQ; q++) vals[q] = warp_sum(vals[q]);

    __shared__ float sm[NT / 32][NQ];
    const int lane = threadIdx.x & 31;
    const int warp = threadIdx.x >> 5;
    if (lane == 0) {
        #pragma unroll
        for (int q = 0; q < NQ; q++) sm[warp][q] = vals[q];
    }
    __syncthreads();

    if (warp == 0) {
        #pragma unroll
        for (int q = 0; q < NQ; q++) {
            float v = (lane < NT / 32) ? sm[lane][q] : 0.0f;
            v = warp_sum(v);
            if (lane == 0) vals[q] = v;
        }
        if (lane == 0) {
            float* dst = g_part + ((size_t)img * GRIDX + blockIdx.x) * 8;
            #pragma unroll
            for (int q = 0; q < NQ; q++) dst[q] = vals[q];
        }
    }

    // -------- last block performs the epilogue --------
    __shared__ bool is_last;
    __syncthreads();   // g_part store (warp 0) ordered before the fence below
    if (threadIdx.x == 0) {
        __threadfence();
        unsigned int v = atomicAdd(&g_count, 1u);
        is_last = (v == (unsigned int)(NBLOCKS - 1));
    }
    __syncthreads();
    if (!is_last) return;

    // 8 warps handle 16 images (2 each)
    __shared__ float agg[BATCH][4];
    for (int b = warp; b < BATCH; b += NT / 32) {
        float s[NQ] = {0.f, 0.f, 0.f, 0.f, 0.f, 0.f, 0.f};
        for (int j = lane; j < GRIDX; j += 32) {
            const float* q = g_part + ((size_t)b * GRIDX + j) * 8;
            #pragma unroll
            for (int k = 0; k < NQ; k++) s[k] += q[k];
        }
        #pragma unroll
        for (int k = 0; k < NQ; k++) s[k] = warp_sum(s[k]);
        if (lane == 0) {
            // s: 0=focal 1=ce 2=p 3=pt 4=t 5=bin 6=bint
            float dice_term = (2.0f * s[3] + SMOOTH) / (s[2] + s[4] + SMOOTH);
            float inter  = s[6];
            float uni    = s[5] + s[4] - s[6];
            float actual = (inter + SMOOTH) / (uni + SMOOTH);
            float d = pred_iou[b] - actual;
            agg[b][0] = s[0];
            agg[b][1] = s[1];
            agg[b][2] = dice_term;
            agg[b][3] = d * d;
        }
    }
    __syncthreads();

    if (threadIdx.x == 0) {
        float fsum = 0.f, csum = 0.f, dsum = 0.f, isum = 0.f;
        #pragma unroll
        for (int b = 0; b < BATCH; b++) {
            fsum += agg[b][0];
            csum += agg[b][1];
            dsum += agg[b][2];
            isum += agg[b][3];
        }
        const float invN = 1.0f / (float)((long long)BATCH * HW);
        float focal    = fsum * invN;
        float dice     = 1.0f - dsum / (float)BATCH;
        float boundary = csum * invN;   // focal + dice + 0.5*(2*mean(ce))
        float iou_loss = 0.1f * (isum / (float)BATCH);
        out[0] = focal + dice + boundary + iou_loss;
        g_count = 0;   // reset for next graph replay
    }
}

extern "C" void kernel_launch(void* const* d_in, const int* in_sizes, int n_in,
                              void* d_out, int out_size) {
    const float4* pred = (const float4*)d_in[0];
    const float4* gt   = (const float4*)d_in[1];
    const float*  piou = (const float*)d_in[2];
    float* out = (float*)d_out;

    dim3 grid(GRIDX, BATCH);
    loss_fused_kernel<<<grid, NT>>>(pred, gt, piou, out);
}

// round 4
// speedup vs baseline: 1.2796x; 1.0713x over previous
#include <cuda_runtime.h>
#include <cstdint>

// Problem constants
#define BATCH    16
#define HW       (1024 * 1024)
#define HW4      (HW / 4)
#define GRIDX    37            // 37*16 = 592 = 148 SMs * 4 CTAs -> one exact wave
#define NT       256
#define NQ       8             // g, tg, lg, omp, tomp, t, bin, bint
#define SMOOTH   1e-6f
#define NBLOCKS  (GRIDX * BATCH)

__device__ float        g_part[BATCH * GRIDX * NQ];
__device__ unsigned int g_count;   // zero-init; self-resets each launch

typedef unsigned long long ull;

// ---------- f32x2 packed helpers (Blackwell FFMA2 path, PTX-only) ----------
__device__ __forceinline__ ull pk2(float lo, float hi) {
    ull r; asm("mov.b64 %0, {%1, %2};" : "=l"(r) : "f"(lo), "f"(hi)); return r;
}
__device__ __forceinline__ void upk2(ull v, float& lo, float& hi) {
    asm("mov.b64 {%0, %1}, %2;" : "=f"(lo), "=f"(hi) : "l"(v));
}
__device__ __forceinline__ ull mul2(ull a, ull b) {
    ull r; asm("mul.rn.f32x2 %0, %1, %2;" : "=l"(r) : "l"(a), "l"(b)); return r;
}
__device__ __forceinline__ ull add2(ull a, ull b) {
    ull r; asm("add.rn.f32x2 %0, %1, %2;" : "=l"(r) : "l"(a), "l"(b)); return r;
}
__device__ __forceinline__ ull fma2(ull a, ull b, ull c) {
    ull r; asm("fma.rn.f32x2 %0, %1, %2, %3;" : "=l"(r) : "l"(a), "l"(b), "l"(c)); return r;
}
__device__ __forceinline__ float ex2a(float x) {
    float r; asm("ex2.approx.f32 %0, %1;" : "=f"(r) : "f"(x)); return r;
}
__device__ __forceinline__ float lg2a(float x) {
    float r; asm("lg2.approx.f32 %0, %1;" : "=f"(r) : "f"(x)); return r;
}
__device__ __forceinline__ float rcpa(float x) {
    float r; asm("rcp.approx.f32 %0, %1;" : "=f"(r) : "f"(x)); return r;
}

struct Accs { ull g, tg, lg, omp, tomp, t, bin, bint; };

// Per-pair math. Identities (t in {0,1}):
//   z = (2t-1)x ; v = exp(-z) = 2^( x * log2e * (1-2t) )
//   ce   = softplus(x) - x*t = ln(1+v) = ln2 * lg2(1+v)
//   omp  = 1 - p_t = sigmoid(-z) = v/(1+v)
//   p    = omp + t*(1-2*omp)      (recovered from sums in epilogue)
//   focal elem = alpha_t * ce * omp^2, alpha_t = 0.75 - 0.5t (factored in epilogue)
//   bin  = (x > 0)  via sign-bit LOP3
__device__ __forceinline__ void group(Accs& A, float x0, float x1, float t0, float t1,
                                      ull Kp, ull Km2, ull ONE2, ull HALF2) {
    ull x2 = pk2(x0, x1);
    ull t2 = pk2(t0, t1);
    ull c2 = fma2(t2, Km2, Kp);       // log2e * (1-2t)
    ull m2 = mul2(x2, c2);
    float m0, m1; upk2(m2, m0, m1);
    float v0 = ex2a(m0), v1 = ex2a(m1);
    ull v2 = pk2(v0, v1);
    ull s2 = add2(v2, ONE2);          // 1+v
    float s0, s1; upk2(s2, s0, s1);
    float r0 = rcpa(s0), r1 = rcpa(s1);
    float l0 = lg2a(s0), l1 = lg2a(s1);
    ull r2 = pk2(r0, r1);
    ull l2 = pk2(l0, l1);
    ull omp2 = mul2(v2, r2);          // v/(1+v)
    ull o2   = mul2(omp2, omp2);
    ull g2   = mul2(l2, o2);          // lg2(s) * omp^2
    A.g    = add2(A.g, g2);
    A.tg   = fma2(t2, g2, A.tg);
    A.lg   = add2(A.lg, l2);
    A.omp  = add2(A.omp, omp2);
    A.tomp = fma2(t2, omp2, A.tomp);
    A.t    = add2(A.t, t2);
    unsigned sb0 = (__float_as_uint(x0) & 0x80000000u) | 0x3F800000u;  // +-1.0
    unsigned sb1 = (__float_as_uint(x1) & 0x80000000u) | 0x3F800000u;
    ull sgn2 = pk2(__uint_as_float(sb0), __uint_as_float(sb1));
    ull bin2 = fma2(sgn2, HALF2, HALF2);   // (x>0) ? 1 : 0
    A.bin  = add2(A.bin, bin2);
    A.bint = fma2(t2, bin2, A.bint);
}

__device__ __forceinline__ float warp_sum(float v) {
    #pragma unroll
    for (int off = 16; off > 0; off >>= 1)
        v += __shfl_xor_sync(0xFFFFFFFFu, v, off);
    return v;
}

__global__ __launch_bounds__(NT, 4)   // 64-reg budget, 4 CTAs/SM, grid = one wave
void loss_fused_kernel(const float4* __restrict__ pred,
                       const float4* __restrict__ gt,
                       const float*  __restrict__ pred_iou,
                       float*        __restrict__ out) {
    const int img = blockIdx.y;
    const float4* px = pred + (size_t)img * HW4;
    const float4* tx = gt   + (size_t)img * HW4;

    const float LOG2E = 1.4426950408889634f;
    const ull Kp    = pk2(LOG2E, LOG2E);
    const ull Km2   = pk2(-2.0f * LOG2E, -2.0f * LOG2E);
    const ull ONE2  = pk2(1.0f, 1.0f);
    const ull HALF2 = pk2(0.5f, 0.5f);

    Accs A;
    A.g = A.tg = A.lg = A.omp = A.tomp = A.t = A.bin = A.bint = pk2(0.0f, 0.0f);

    const int stride = GRIDX * NT;
    int i = blockIdx.x * NT + threadIdx.x;

    // unroll-2: 4 back-to-back LDG.128 per iteration for MLP
    for (; i + stride < HW4; i += 2 * stride) {
        float4 a0 = __ldg(px + i);
        float4 b0 = __ldg(tx + i);
        float4 a1 = __ldg(px + i + stride);
        float4 b1 = __ldg(tx + i + stride);
        group(A, a0.x, a0.y, b0.x, b0.y, Kp, Km2, ONE2, HALF2);
        group(A, a0.z, a0.w, b0.z, b0.w, Kp, Km2, ONE2, HALF2);
        group(A, a1.x, a1.y, b1.x, b1.y, Kp, Km2, ONE2, HALF2);
        group(A, a1.z, a1.w, b1.z, b1.w, Kp, Km2, ONE2, HALF2);
    }
    if (i < HW4) {
        float4 a0 = __ldg(px + i);
        float4 b0 = __ldg(tx + i);
        group(A, a0.x, a0.y, b0.x, b0.y, Kp, Km2, ONE2, HALF2);
        group(A, a0.z, a0.w, b0.z, b0.w, Kp, Km2, ONE2, HALF2);
    }

    // collapse packed halves (lo+hi are independent element partitions)
    float vals[NQ];
    {
        float lo, hi;
        upk2(A.g,    lo, hi); vals[0] = lo + hi;
        upk2(A.tg,   lo, hi); vals[1] = lo + hi;
        upk2(A.lg,   lo, hi); vals[2] = lo + hi;
        upk2(A.omp,  lo, hi); vals[3] = lo + hi;
        upk2(A.tomp, lo, hi); vals[4] = lo + hi;
        upk2(A.t,    lo, hi); vals[5] = lo + hi;
        upk2(A.bin,  lo, hi); vals[6] = lo + hi;
        upk2(A.bint, lo, hi); vals[7] = lo + hi;
    }

    // -------- block reduction --------
    #pragma unroll
    for (int q = 0; q < NQ; q++) vals[q] = warp_sum(vals[q]);

    __shared__ float sm[NT / 32][NQ];
    const int lane = threadIdx.x & 31;
    const int warp = threadIdx.x >> 5;
    if (lane == 0) {
        #pragma unroll
        for (int q = 0; q < NQ; q++) sm[warp][q] = vals[q];
    }
    __syncthreads();

    __shared__ bool is_last;
    if (warp == 0) {
        #pragma unroll
        for (int q = 0; q < NQ; q++) {
            float v = (lane < NT / 32) ? sm[lane][q] : 0.0f;
            v = warp_sum(v);
            if (lane == 0) vals[q] = v;
        }
        if (lane == 0) {
            float* dst = g_part + ((size_t)img * GRIDX + blockIdx.x) * NQ;
            #pragma unroll
            for (int q = 0; q < NQ; q++) dst[q] = vals[q];
            __threadfence();   // same thread that stored -> correctly ordered
            unsigned int v = atomicAdd(&g_count, 1u);
            is_last = (v == (unsigned int)(NBLOCKS - 1));
        }
    }
    __syncthreads();
    if (!is_last) return;

    // -------- epilogue: last block reduces 592 partials --------
    __shared__ float agg[BATCH][4];
    for (int b = warp; b < BATCH; b += NT / 32) {
        float s[NQ] = {0.f, 0.f, 0.f, 0.f, 0.f, 0.f, 0.f, 0.f};
        for (int j = lane; j < GRIDX; j += 32) {
            const float* q = g_part + ((size_t)b * GRIDX + j) * NQ;
            #pragma unroll
            for (int k = 0; k < NQ; k++) s[k] += q[k];
        }
        #pragma unroll
        for (int k = 0; k < NQ; k++) s[k] = warp_sum(s[k]);
        if (lane == 0) {
            // s: 0=g 1=tg 2=lg 3=omp 4=tomp 5=t 6=bin 7=bint
            float Sp  = s[3] + s[5] - 2.0f * s[4];   // sum p
            float Spt = s[5] - s[4];                 // sum p*t
            float dice_term = (2.0f * Spt + SMOOTH) / (Sp + s[5] + SMOOTH);
            float inter  = s[7];
            float uni    = s[6] + s[5] - s[7];
            float actual = (inter + SMOOTH) / (uni + SMOOTH);
            float d = pred_iou[b] - actual;
            agg[b][0] = 0.75f * s[0] - 0.5f * s[1];  // focal partial (x ln2 later)
            agg[b][1] = s[2];                        // sum lg2(s)  (x ln2 = sum ce)
            agg[b][2] = dice_term;
            agg[b][3] = d * d;
        }
    }
    __syncthreads();

    if (threadIdx.x == 0) {
        float fsum = 0.f, csum = 0.f, dsum = 0.f, isum = 0.f;
        #pragma unroll
        for (int b = 0; b < BATCH; b++) {
            fsum += agg[b][0];
            csum += agg[b][1];
            dsum += agg[b][2];
            isum += agg[b][3];
        }
        const float LN2  = 0.6931471805599453f;
        const float invN = 1.0f / (float)((long long)BATCH * HW);
        float focal    = LN2 * fsum * invN;
        float dice     = 1.0f - dsum / (float)BATCH;
        float boundary = LN2 * csum * invN;          // = mean(ce) = 0.5 * (2*mean(ce))
        float iou_loss = 0.1f * (isum / (float)BATCH);
        out[0] = focal + dice + boundary + iou_loss;
        g_count = 0;   // reset for next graph replay
    }
}

extern "C" void kernel_launch(void* const* d_in, const int* in_sizes, int n_in,
                              void* d_out, int out_size) {
    const float4* pred = (const float4*)d_in[0];
    const float4* gt   = (const float4*)d_in[1];
    const float*  piou = (const float*)d_in[2];
    float* out = (float*)d_out;

    dim3 grid(GRIDX, BATCH);
    loss_fused_kernel<<<grid, NT>>>(pred, gt, piou, out);
}